// round 6
// baseline (speedup 1.0000x reference)
#include <cuda_runtime.h>

typedef unsigned long long u64;

#define NL    19
#define DIM   6
#define LANES 3                 // packed f32x2 lanes per thread
#define ROWS  (2 * LANES)       // 6 rows per thread
#define TPB   128

// ---------------- packed f32x2 helpers (Blackwell sm_103a) ----------------
__device__ __forceinline__ u64 fma2(u64 a, u64 b, u64 c) {
    u64 d; asm("fma.rn.f32x2 %0, %1, %2, %3;" : "=l"(d) : "l"(a), "l"(b), "l"(c)); return d;
}
__device__ __forceinline__ u64 add2(u64 a, u64 b) {
    u64 d; asm("add.rn.f32x2 %0, %1, %2;" : "=l"(d) : "l"(a), "l"(b)); return d;
}
__device__ __forceinline__ u64 pack2(float x, float y) {
    u64 d; asm("mov.b64 %0, {%1, %2};" : "=l"(d) : "f"(x), "f"(y)); return d;
}
__device__ __forceinline__ void unpack2(u64 v, float &x, float &y) {
    asm("mov.b64 {%0, %1}, %2;" : "=f"(x), "=f"(y) : "l"(v));
}

__global__ void __launch_bounds__(TPB, 3)     // <=168 regs, 12 warps/SM, no spills
mlp_kernel(const float* __restrict__ X,
           const float* __restrict__ Ws,
           const float* __restrict__ bs,
           const float* __restrict__ bounds,
           float* __restrict__ out,
           int B)
{
    __shared__ __align__(16) u64 sW[NL][DIM * DIM];   // packed {w,w}
    __shared__ __align__(16) u64 sB[NL][DIM];         // packed {b,b}
    __shared__ __align__(16) u64 sScale[DIM], sOff[DIM];
    __shared__ u64 sRes[LANES * DIM][TPB];            // residual parking (SoA)

    for (int i = threadIdx.x; i < NL * DIM * DIM; i += blockDim.x) {
        float w = Ws[i];
        sW[i / (DIM * DIM)][i % (DIM * DIM)] = pack2(w, w);
    }
    for (int i = threadIdx.x; i < NL * DIM; i += blockDim.x) {
        float b = bs[i];
        sB[i / DIM][i % DIM] = pack2(b, b);
    }
    if (threadIdx.x < DIM) {
        float lo = bounds[2 * threadIdx.x];
        float hi = bounds[2 * threadIdx.x + 1];
        float s  = 1.0f / (hi - lo);
        float o  = -lo * s;
        sScale[threadIdx.x] = pack2(s, s);
        sOff[threadIdx.x]   = pack2(o, o);
    }
    __syncthreads();

    long long tid  = (long long)blockIdx.x * blockDim.x + threadIdx.x;
    long long base = tid * ROWS;
    if (base >= B) return;
    const int lt = threadIdx.x;

    // LIN over output-neuron pairs; weights/bias via LDS.128, each feeding 6 fma2
#define LIN(L, IN, OUT) do {                                                    \
    _Pragma("unroll")                                                           \
    for (int j = 0; j < DIM; j += 2) {                                          \
        ulonglong2 bb = *reinterpret_cast<const ulonglong2*>(&sB[(L)][j]);      \
        u64 a0[LANES], a1[LANES];                                               \
        _Pragma("unroll")                                                       \
        for (int p = 0; p < LANES; p++) { a0[p] = bb.x; a1[p] = bb.y; }         \
        _Pragma("unroll")                                                       \
        for (int kk = 0; kk < DIM; kk += 2) {                                   \
            ulonglong2 w0 = *reinterpret_cast<const ulonglong2*>(               \
                                &sW[(L)][j * DIM + kk]);                        \
            ulonglong2 w1 = *reinterpret_cast<const ulonglong2*>(               \
                                &sW[(L)][(j + 1) * DIM + kk]);                  \
            _Pragma("unroll")                                                   \
            for (int p = 0; p < LANES; p++) {                                   \
                a0[p] = fma2(IN[p][kk],     w0.x, a0[p]);                       \
                a0[p] = fma2(IN[p][kk + 1], w0.y, a0[p]);                       \
                a1[p] = fma2(IN[p][kk],     w1.x, a1[p]);                       \
                a1[p] = fma2(IN[p][kk + 1], w1.y, a1[p]);                       \
            }                                                                   \
        }                                                                       \
        _Pragma("unroll")                                                       \
        for (int p = 0; p < LANES; p++) { OUT[p][j] = a0[p]; OUT[p][j+1] = a1[p]; } \
    } } while (0)

    // lrelu per half: FMUL-imm (fma pipe, rt=1) + FMNMX (alu pipe)
#define LRELU(A) do {                                                          \
    _Pragma("unroll")                                                          \
    for (int p = 0; p < LANES; p++) {                                          \
        _Pragma("unroll")                                                      \
        for (int j = 0; j < DIM; j++) {                                        \
            float lo_, hi_;                                                    \
            unpack2(A[p][j], lo_, hi_);                                        \
            lo_ = fmaxf(lo_, 0.01f * lo_);                                     \
            hi_ = fmaxf(hi_, 0.01f * hi_);                                     \
            A[p][j] = pack2(lo_, hi_);                                         \
        }                                                                      \
    } } while (0)

    if (base + ROWS <= B) {
        // ---------- fast path: 6 full rows ----------
        u64 w[LANES][DIM], t[LANES][DIM];

        const float4* Xv = reinterpret_cast<const float4*>(X + base * DIM);
#pragma unroll
        for (int p = 0; p < LANES; p++) {
            float4 q0 = Xv[3 * p + 0], q1 = Xv[3 * p + 1], q2 = Xv[3 * p + 2];
            w[p][0] = fma2(pack2(q0.x, q1.z), sScale[0], sOff[0]);
            w[p][1] = fma2(pack2(q0.y, q1.w), sScale[1], sOff[1]);
            w[p][2] = fma2(pack2(q0.z, q2.x), sScale[2], sOff[2]);
            w[p][3] = fma2(pack2(q0.w, q2.y), sScale[3], sOff[3]);
            w[p][4] = fma2(pack2(q1.x, q2.z), sScale[4], sOff[4]);
            w[p][5] = fma2(pack2(q1.y, q2.w), sScale[5], sOff[5]);
        }

#pragma unroll
        for (int blk = 0; blk < 4; blk++) {
            const int i0 = blk * 4;
#pragma unroll
            for (int p = 0; p < LANES; p++)
#pragma unroll
                for (int j = 0; j < DIM; j++) sRes[p * DIM + j][lt] = w[p][j];

            LIN(i0 + 0, w, t); LRELU(t);
            LIN(i0 + 1, t, w); LRELU(w);
            LIN(i0 + 2, w, t); LRELU(t);
            LIN(i0 + 3, t, w);
#pragma unroll
            for (int p = 0; p < LANES; p++)
#pragma unroll
                for (int j = 0; j < DIM; j++)
                    w[p][j] = add2(w[p][j], sRes[p * DIM + j][lt]);
        }
        LIN(16, w, t); LRELU(t);
        LIN(17, t, w); LRELU(w);
        LIN(18, w, t);

        float4* Ov = reinterpret_cast<float4*>(out + base * DIM);
#pragma unroll
        for (int p = 0; p < LANES; p++) {
            float a0, b0, a1, b1, a2, b2, a3, b3, a4, b4, a5, b5;
            unpack2(t[p][0], a0, b0); unpack2(t[p][1], a1, b1);
            unpack2(t[p][2], a2, b2); unpack2(t[p][3], a3, b3);
            unpack2(t[p][4], a4, b4); unpack2(t[p][5], a5, b5);
            Ov[3 * p + 0] = make_float4(a0, a1, a2, a3);
            Ov[3 * p + 1] = make_float4(a4, a5, b0, b1);
            Ov[3 * p + 2] = make_float4(b2, b3, b4, b5);
        }
    } else {
        // ---------- tail path: scalar per-row (last few rows; B%6 != 0) ----------
        const float* sWf = reinterpret_cast<const float*>(sW);      // stride 2 (packed dup)
        const float* sBf = reinterpret_cast<const float*>(sB);
        const float* sSf = reinterpret_cast<const float*>(sScale);
        const float* sOf = reinterpret_cast<const float*>(sOff);

        for (long long r = base; r < B; r++) {
            float x[DIM], y[DIM], rs[DIM];
            for (int k = 0; k < DIM; k++)
                x[k] = X[r * DIM + k] * sSf[2 * k] + sOf[2 * k];

            auto lin_s = [&](int L, const float* in, float* o) {
                for (int j = 0; j < DIM; j++) {
                    float a = sBf[(L * DIM + j) * 2];
                    for (int k = 0; k < DIM; k++)
                        a = fmaf(in[k], sWf[(L * DIM * DIM + j * DIM + k) * 2], a);
                    o[j] = a;
                }
            };
            auto lrelu_s = [&](float* v) {
                for (int j = 0; j < DIM; j++) v[j] = fmaxf(v[j], 0.01f * v[j]);
            };

            for (int blk = 0; blk < 4; blk++) {
                int i0 = blk * 4;
                for (int k = 0; k < DIM; k++) rs[k] = x[k];
                lin_s(i0 + 0, x, y); lrelu_s(y);
                lin_s(i0 + 1, y, x); lrelu_s(x);
                lin_s(i0 + 2, x, y); lrelu_s(y);
                lin_s(i0 + 3, y, x);
                for (int k = 0; k < DIM; k++) x[k] += rs[k];
            }
            lin_s(16, x, y); lrelu_s(y);
            lin_s(17, y, x); lrelu_s(x);
            lin_s(18, x, y);
            for (int k = 0; k < DIM; k++) out[r * DIM + k] = y[k];
        }
    }
#undef LIN
#undef LRELU
}

extern "C" void kernel_launch(void* const* d_in, const int* in_sizes, int n_in,
                              void* d_out, int out_size)
{
    const float* X      = (const float*)d_in[0];
    const float* Ws     = (const float*)d_in[1];
    const float* bs     = (const float*)d_in[2];
    const float* bounds = (const float*)d_in[3];
    float* out = (float*)d_out;

    int B = in_sizes[0] / DIM;
    long long tiles = ((long long)B + ROWS - 1) / ROWS;
    int blocks = (int)((tiles + TPB - 1) / TPB);

    mlp_kernel<<<blocks, TPB>>>(X, Ws, bs, bounds, out, B);
}

// round 7
// speedup vs baseline: 1.1385x; 1.1385x over previous
#include <cuda_runtime.h>

typedef unsigned long long u64;

#define NL    19
#define DIM   6
#define LANES 2                 // packed f32x2 lanes per thread
#define ROWS  (2 * LANES)       // 4 rows per thread
#define TPB   256

// ---------------- packed f32x2 helpers (Blackwell sm_103a) ----------------
__device__ __forceinline__ u64 fma2(u64 a, u64 b, u64 c) {
    u64 d; asm("fma.rn.f32x2 %0, %1, %2, %3;" : "=l"(d) : "l"(a), "l"(b), "l"(c)); return d;
}
__device__ __forceinline__ u64 mul2(u64 a, u64 b) {
    u64 d; asm("mul.rn.f32x2 %0, %1, %2;" : "=l"(d) : "l"(a), "l"(b)); return d;
}
__device__ __forceinline__ u64 add2(u64 a, u64 b) {
    u64 d; asm("add.rn.f32x2 %0, %1, %2;" : "=l"(d) : "l"(a), "l"(b)); return d;
}
__device__ __forceinline__ u64 pack2(float x, float y) {
    u64 d; asm("mov.b64 %0, {%1, %2};" : "=l"(d) : "f"(x), "f"(y)); return d;
}
__device__ __forceinline__ void unpack2(u64 v, float &x, float &y) {
    asm("mov.b64 {%0, %1}, %2;" : "=f"(x), "=f"(y) : "l"(v));
}
// forced 128-bit shared load (2 packed weights per LDS.128)
__device__ __forceinline__ void lds_v2(unsigned saddr, u64 &a, u64 &b) {
    asm("ld.shared.v2.u64 {%0, %1}, [%2];" : "=l"(a), "=l"(b) : "r"(saddr));
}

// lrelu(x) = 0.505*x + 0.495*|x|, fully packed (no unpack/pack churn)
#define LRELU_A 0.505f
#define LRELU_B 0.495f

__global__ void __launch_bounds__(TPB, 2)     // 128 regs, 16 warps/SM (best-measured cfg)
mlp_kernel(const float* __restrict__ X,
           const float* __restrict__ Ws,
           const float* __restrict__ bs,
           const float* __restrict__ bounds,
           float* __restrict__ out,
           int B)
{
    __shared__ __align__(16) u64 sW[NL][DIM * DIM];   // packed {w,w}; layer stride 288B
    __shared__ __align__(16) u64 sB[NL][DIM + 2];     // packed {b,b}; padded to 64B stride
    __shared__ __align__(16) u64 sScale[DIM], sOff[DIM];

    for (int i = threadIdx.x; i < NL * DIM * DIM; i += blockDim.x) {
        float w = Ws[i];
        sW[i / (DIM * DIM)][i % (DIM * DIM)] = pack2(w, w);
    }
    for (int i = threadIdx.x; i < NL * DIM; i += blockDim.x) {
        float b = bs[i];
        sB[i / DIM][i % DIM] = pack2(b, b);
    }
    if (threadIdx.x < DIM) {
        float lo = bounds[2 * threadIdx.x];
        float hi = bounds[2 * threadIdx.x + 1];
        float s  = 1.0f / (hi - lo);
        float o  = -lo * s;
        sScale[threadIdx.x] = pack2(s, s);
        sOff[threadIdx.x]   = pack2(o, o);
    }
    __syncthreads();

    const unsigned swb = (unsigned)__cvta_generic_to_shared(&sW[0][0]);
    const unsigned sbb = (unsigned)__cvta_generic_to_shared(&sB[0][0]);

    long long tid  = (long long)blockIdx.x * blockDim.x + threadIdx.x;
    long long base = tid * ROWS;
    if (base >= B) return;

    const u64 CA = pack2(LRELU_A, LRELU_A);
    const u64 CB = pack2(LRELU_B, LRELU_B);

    // LIN over output-neuron pairs; every shared access is a forced LDS.128.
    // 18 weight + 3 bias LDS.128 per layer; each weight feeds LANES fma2.
#define LIN(L, IN, OUT) do {                                                    \
    _Pragma("unroll")                                                           \
    for (int j = 0; j < DIM; j += 2) {                                          \
        u64 bb0, bb1;                                                           \
        lds_v2(sbb + (unsigned)((L) * (DIM + 2) + j) * 8u, bb0, bb1);           \
        u64 a0[LANES], a1[LANES];                                               \
        _Pragma("unroll")                                                       \
        for (int p = 0; p < LANES; p++) { a0[p] = bb0; a1[p] = bb1; }           \
        _Pragma("unroll")                                                       \
        for (int kk = 0; kk < DIM; kk += 2) {                                   \
            u64 w0x, w0y, w1x, w1y;                                             \
            lds_v2(swb + (unsigned)((L) * 36 + j * DIM + kk) * 8u, w0x, w0y);   \
            lds_v2(swb + (unsigned)((L) * 36 + (j + 1) * DIM + kk) * 8u, w1x, w1y); \
            _Pragma("unroll")                                                   \
            for (int p = 0; p < LANES; p++) {                                   \
                a0[p] = fma2(IN[p][kk],     w0x, a0[p]);                        \
                a0[p] = fma2(IN[p][kk + 1], w0y, a0[p]);                        \
                a1[p] = fma2(IN[p][kk],     w1x, a1[p]);                        \
                a1[p] = fma2(IN[p][kk + 1], w1y, a1[p]);                        \
            }                                                                   \
        }                                                                       \
        _Pragma("unroll")                                                       \
        for (int p = 0; p < LANES; p++) { OUT[p][j] = a0[p]; OUT[p][j+1] = a1[p]; } \
    } } while (0)

#define LRELU(A) do {                                                          \
    _Pragma("unroll")                                                          \
    for (int p = 0; p < LANES; p++) {                                          \
        _Pragma("unroll")                                                      \
        for (int j = 0; j < DIM; j++) {                                        \
            u64 ab = A[p][j] & 0x7FFFFFFF7FFFFFFFULL;                          \
            A[p][j] = fma2(A[p][j], CA, mul2(ab, CB));                         \
        }                                                                      \
    } } while (0)

    if (base + ROWS <= B) {
        // ---------- fast path: 4 full rows ----------
        u64 w[LANES][DIM], t[LANES][DIM], res[LANES][DIM];

        const float4* Xv = reinterpret_cast<const float4*>(X + base * DIM);
#pragma unroll
        for (int p = 0; p < LANES; p++) {
            float4 q0 = Xv[3 * p + 0], q1 = Xv[3 * p + 1], q2 = Xv[3 * p + 2];
            w[p][0] = fma2(pack2(q0.x, q1.z), sScale[0], sOff[0]);
            w[p][1] = fma2(pack2(q0.y, q1.w), sScale[1], sOff[1]);
            w[p][2] = fma2(pack2(q0.z, q2.x), sScale[2], sOff[2]);
            w[p][3] = fma2(pack2(q0.w, q2.y), sScale[3], sOff[3]);
            w[p][4] = fma2(pack2(q1.x, q2.z), sScale[4], sOff[4]);
            w[p][5] = fma2(pack2(q1.y, q2.w), sScale[5], sOff[5]);
        }

#pragma unroll
        for (int blk = 0; blk < 4; blk++) {
            const int i0 = blk * 4;
#pragma unroll
            for (int p = 0; p < LANES; p++)
#pragma unroll
                for (int j = 0; j < DIM; j++) res[p][j] = w[p][j];

            LIN(i0 + 0, w, t); LRELU(t);
            LIN(i0 + 1, t, w); LRELU(w);
            LIN(i0 + 2, w, t); LRELU(t);
            LIN(i0 + 3, t, w);
#pragma unroll
            for (int p = 0; p < LANES; p++)
#pragma unroll
                for (int j = 0; j < DIM; j++) w[p][j] = add2(w[p][j], res[p][j]);
        }
        LIN(16, w, t); LRELU(t);
        LIN(17, t, w); LRELU(w);
        LIN(18, w, t);

        float4* Ov = reinterpret_cast<float4*>(out + base * DIM);
#pragma unroll
        for (int p = 0; p < LANES; p++) {
            float a0, b0, a1, b1, a2, b2, a3, b3, a4, b4, a5, b5;
            unpack2(t[p][0], a0, b0); unpack2(t[p][1], a1, b1);
            unpack2(t[p][2], a2, b2); unpack2(t[p][3], a3, b3);
            unpack2(t[p][4], a4, b4); unpack2(t[p][5], a5, b5);
            Ov[3 * p + 0] = make_float4(a0, a1, a2, a3);
            Ov[3 * p + 1] = make_float4(a4, a5, b0, b1);
            Ov[3 * p + 2] = make_float4(b2, b3, b4, b5);
        }
    } else {
        // ---------- tail path: scalar per-row (not taken when B%4==0) ----------
        const float* sWf = reinterpret_cast<const float*>(sW);
        const float* sBf = reinterpret_cast<const float*>(sB);
        const float* sSf = reinterpret_cast<const float*>(sScale);
        const float* sOf = reinterpret_cast<const float*>(sOff);

        for (long long r = base; r < B; r++) {
            float x[DIM], y[DIM], rs[DIM];
            for (int k = 0; k < DIM; k++)
                x[k] = X[r * DIM + k] * sSf[2 * k] + sOf[2 * k];

            auto lin_s = [&](int L, const float* in, float* o) {
                for (int j = 0; j < DIM; j++) {
                    float a = sBf[(L * (DIM + 2) + j) * 2];
                    for (int k = 0; k < DIM; k++)
                        a = fmaf(in[k], sWf[(L * DIM * DIM + j * DIM + k) * 2], a);
                    o[j] = a;
                }
            };
            auto lrelu_s = [&](float* v) {
                for (int j = 0; j < DIM; j++) v[j] = fmaxf(v[j], 0.01f * v[j]);
            };

            for (int blk = 0; blk < 4; blk++) {
                int i0 = blk * 4;
                for (int k = 0; k < DIM; k++) rs[k] = x[k];
                lin_s(i0 + 0, x, y); lrelu_s(y);
                lin_s(i0 + 1, y, x); lrelu_s(x);
                lin_s(i0 + 2, x, y); lrelu_s(y);
                lin_s(i0 + 3, y, x);
                for (int k = 0; k < DIM; k++) x[k] += rs[k];
            }
            lin_s(16, x, y); lrelu_s(y);
            lin_s(17, y, x); lrelu_s(x);
            lin_s(18, x, y);
            for (int k = 0; k < DIM; k++) out[r * DIM + k] = y[k];
        }
    }
#undef LIN
#undef LRELU
}

extern "C" void kernel_launch(void* const* d_in, const int* in_sizes, int n_in,
                              void* d_out, int out_size)
{
    const float* X      = (const float*)d_in[0];
    const float* Ws     = (const float*)d_in[1];
    const float* bs     = (const float*)d_in[2];
    const float* bounds = (const float*)d_in[3];
    float* out = (float*)d_out;

    int B = in_sizes[0] / DIM;
    long long tiles = ((long long)B + ROWS - 1) / ROWS;
    int blocks = (int)((tiles + TPB - 1) / TPB);

    mlp_kernel<<<blocks, TPB>>>(X, Ws, bs, bounds, out, B);
}

// round 8
// speedup vs baseline: 1.1635x; 1.0220x over previous
#include <cuda_runtime.h>

typedef unsigned long long u64;

#define NL    19
#define DIM   6
#define LANES 2                 // packed f32x2 lanes per thread
#define ROWS  (2 * LANES)       // 4 rows per thread
#define TPB   256

// ---------------- packed f32x2 helpers (Blackwell sm_103a) ----------------
__device__ __forceinline__ u64 fma2(u64 a, u64 b, u64 c) {
    u64 d; asm("fma.rn.f32x2 %0, %1, %2, %3;" : "=l"(d) : "l"(a), "l"(b), "l"(c)); return d;
}
__device__ __forceinline__ u64 mul2(u64 a, u64 b) {
    u64 d; asm("mul.rn.f32x2 %0, %1, %2;" : "=l"(d) : "l"(a), "l"(b)); return d;
}
__device__ __forceinline__ u64 add2(u64 a, u64 b) {
    u64 d; asm("add.rn.f32x2 %0, %1, %2;" : "=l"(d) : "l"(a), "l"(b)); return d;
}
__device__ __forceinline__ u64 pack2(float x, float y) {
    u64 d; asm("mov.b64 %0, {%1, %2};" : "=l"(d) : "f"(x), "f"(y)); return d;
}
__device__ __forceinline__ void unpack2(u64 v, float &x, float &y) {
    asm("mov.b64 {%0, %1}, %2;" : "=f"(x), "=f"(y) : "l"(v));
}

// lrelu(x) = 0.505*x + 0.495*|x|, fully packed
#define LRELU_A 0.505f
#define LRELU_B 0.495f

// ---------------- constant-bank weight storage ----------------
struct Consts {
    u64 W[NL][DIM * DIM];   // packed {w,w}
    u64 B[NL][DIM];         // packed {b,b}
    u64 scale[DIM], off[DIM];
};
__device__   Consts g_stage;    // staging (written by prep kernel)
__constant__ Consts c_c;        // read by main kernel via const port

__global__ void prep_kernel(const float* __restrict__ Ws,
                            const float* __restrict__ bs,
                            const float* __restrict__ bounds)
{
    int i = threadIdx.x + blockIdx.x * blockDim.x;
    if (i < NL * DIM * DIM) {
        float w = Ws[i];
        g_stage.W[i / (DIM * DIM)][i % (DIM * DIM)] = pack2(w, w);
    }
    if (i < NL * DIM) {
        float b = bs[i];
        g_stage.B[i / DIM][i % DIM] = pack2(b, b);
    }
    if (i < DIM) {
        float lo = bounds[2 * i];
        float hi = bounds[2 * i + 1];
        float s  = 1.0f / (hi - lo);
        float o  = -lo * s;
        g_stage.scale[i] = pack2(s, s);
        g_stage.off[i]   = pack2(o, o);
    }
}

__global__ void __launch_bounds__(TPB, 2)     // <=128 regs, 16 warps/SM
mlp_kernel(const float* __restrict__ X,
           float* __restrict__ out,
           int B)
{
    long long tid  = (long long)blockIdx.x * blockDim.x + threadIdx.x;
    long long base = tid * ROWS;
    if (base >= B) return;

    const u64 CA = pack2(LRELU_A, LRELU_A);
    const u64 CB = pack2(LRELU_B, LRELU_B);

    // LIN: weights/bias from CONSTANT bank (uniform compile-time offsets -> LDCU/UR),
    // zero shared/L1 traffic, each const value feeds LANES fma2.
#define LIN(L, IN, OUT) do {                                                   \
    _Pragma("unroll")                                                          \
    for (int j = 0; j < DIM; j++) {                                            \
        u64 acc[LANES];                                                        \
        u64 bb = c_c.B[(L)][j];                                                \
        _Pragma("unroll")                                                      \
        for (int p = 0; p < LANES; p++) acc[p] = bb;                           \
        _Pragma("unroll")                                                      \
        for (int k = 0; k < DIM; k++) {                                        \
            u64 ww = c_c.W[(L)][j * DIM + k];                                  \
            _Pragma("unroll")                                                  \
            for (int p = 0; p < LANES; p++) acc[p] = fma2(IN[p][k], ww, acc[p]);\
        }                                                                      \
        _Pragma("unroll")                                                      \
        for (int p = 0; p < LANES; p++) OUT[p][j] = acc[p];                    \
    } } while (0)

#define LRELU(A) do {                                                          \
    _Pragma("unroll")                                                          \
    for (int p = 0; p < LANES; p++) {                                          \
        _Pragma("unroll")                                                      \
        for (int j = 0; j < DIM; j++) {                                        \
            u64 ab = A[p][j] & 0x7FFFFFFF7FFFFFFFULL;                          \
            A[p][j] = fma2(A[p][j], CA, mul2(ab, CB));                         \
        }                                                                      \
    } } while (0)

    if (base + ROWS <= B) {
        // ---------- fast path: 4 full rows ----------
        u64 w[LANES][DIM], t[LANES][DIM], res[LANES][DIM];

        const float4* Xv = reinterpret_cast<const float4*>(X + base * DIM);
#pragma unroll
        for (int p = 0; p < LANES; p++) {
            float4 q0 = Xv[3 * p + 0], q1 = Xv[3 * p + 1], q2 = Xv[3 * p + 2];
            w[p][0] = fma2(pack2(q0.x, q1.z), c_c.scale[0], c_c.off[0]);
            w[p][1] = fma2(pack2(q0.y, q1.w), c_c.scale[1], c_c.off[1]);
            w[p][2] = fma2(pack2(q0.z, q2.x), c_c.scale[2], c_c.off[2]);
            w[p][3] = fma2(pack2(q0.w, q2.y), c_c.scale[3], c_c.off[3]);
            w[p][4] = fma2(pack2(q1.x, q2.z), c_c.scale[4], c_c.off[4]);
            w[p][5] = fma2(pack2(q1.y, q2.w), c_c.scale[5], c_c.off[5]);
        }

#pragma unroll
        for (int blk = 0; blk < 4; blk++) {
            const int i0 = blk * 4;
#pragma unroll
            for (int p = 0; p < LANES; p++)
#pragma unroll
                for (int j = 0; j < DIM; j++) res[p][j] = w[p][j];

            LIN(i0 + 0, w, t); LRELU(t);
            LIN(i0 + 1, t, w); LRELU(w);
            LIN(i0 + 2, w, t); LRELU(t);
            LIN(i0 + 3, t, w);
#pragma unroll
            for (int p = 0; p < LANES; p++)
#pragma unroll
                for (int j = 0; j < DIM; j++) w[p][j] = add2(w[p][j], res[p][j]);
        }
        LIN(16, w, t); LRELU(t);
        LIN(17, t, w); LRELU(w);
        LIN(18, w, t);

        float4* Ov = reinterpret_cast<float4*>(out + base * DIM);
#pragma unroll
        for (int p = 0; p < LANES; p++) {
            float a0, b0, a1, b1, a2, b2, a3, b3, a4, b4, a5, b5;
            unpack2(t[p][0], a0, b0); unpack2(t[p][1], a1, b1);
            unpack2(t[p][2], a2, b2); unpack2(t[p][3], a3, b3);
            unpack2(t[p][4], a4, b4); unpack2(t[p][5], a5, b5);
            Ov[3 * p + 0] = make_float4(a0, a1, a2, a3);
            Ov[3 * p + 1] = make_float4(a4, a5, b0, b1);
            Ov[3 * p + 2] = make_float4(b2, b3, b4, b5);
        }
    } else {
        // ---------- tail path: scalar per-row (not taken when B%4==0) ----------
        for (long long r = base; r < B; r++) {
            float x[DIM], y[DIM], rs[DIM];
            for (int k = 0; k < DIM; k++) {
                float s, o, dummy;
                unpack2(c_c.scale[k], s, dummy);
                unpack2(c_c.off[k],   o, dummy);
                x[k] = X[r * DIM + k] * s + o;
            }

            auto lin_s = [&](int L, const float* in, float* o) {
                for (int j = 0; j < DIM; j++) {
                    float a, d0;
                    unpack2(c_c.B[L][j], a, d0);
                    for (int k = 0; k < DIM; k++) {
                        float wv, d1;
                        unpack2(c_c.W[L][j * DIM + k], wv, d1);
                        a = fmaf(in[k], wv, a);
                    }
                    o[j] = a;
                }
            };
            auto lrelu_s = [&](float* v) {
                for (int j = 0; j < DIM; j++) v[j] = fmaxf(v[j], 0.01f * v[j]);
            };

            for (int blk = 0; blk < 4; blk++) {
                int i0 = blk * 4;
                for (int k = 0; k < DIM; k++) rs[k] = x[k];
                lin_s(i0 + 0, x, y); lrelu_s(y);
                lin_s(i0 + 1, y, x); lrelu_s(x);
                lin_s(i0 + 2, x, y); lrelu_s(y);
                lin_s(i0 + 3, y, x);
                for (int k = 0; k < DIM; k++) x[k] += rs[k];
            }
            lin_s(16, x, y); lrelu_s(y);
            lin_s(17, y, x); lrelu_s(x);
            lin_s(18, x, y);
            for (int k = 0; k < DIM; k++) out[r * DIM + k] = y[k];
        }
    }
#undef LIN
#undef LRELU
}

extern "C" void kernel_launch(void* const* d_in, const int* in_sizes, int n_in,
                              void* d_out, int out_size)
{
    const float* X      = (const float*)d_in[0];
    const float* Ws     = (const float*)d_in[1];
    const float* bs     = (const float*)d_in[2];
    const float* bounds = (const float*)d_in[3];
    float* out = (float*)d_out;

    int B = in_sizes[0] / DIM;

    // 1) pack weights into staging struct (device global, no alloc)
    prep_kernel<<<3, 256>>>(Ws, bs, bounds);

    // 2) staging -> constant bank (D2D memcpy node, graph-capturable)
    void* stage_ptr = nullptr;
    cudaGetSymbolAddress(&stage_ptr, g_stage);
    cudaMemcpyToSymbolAsync(c_c, stage_ptr, sizeof(Consts), 0,
                            cudaMemcpyDeviceToDevice, 0);

    // 3) main kernel
    long long tiles = ((long long)B + ROWS - 1) / ROWS;
    int blocks = (int)((tiles + TPB - 1) / TPB);
    mlp_kernel<<<blocks, TPB>>>(X, out, B);
}

// round 9
// speedup vs baseline: 1.2180x; 1.0468x over previous
#include <cuda_runtime.h>

typedef unsigned long long u64;

#define NL    19
#define DIM   6
#define LANES 2                 // packed f32x2 lanes per thread
#define ROWS  (2 * LANES)       // 4 rows per thread
#define TPB   256

// ---------------- packed f32x2 helpers (Blackwell sm_103a) ----------------
__device__ __forceinline__ u64 fma2(u64 a, u64 b, u64 c) {
    u64 d; asm("fma.rn.f32x2 %0, %1, %2, %3;" : "=l"(d) : "l"(a), "l"(b), "l"(c)); return d;
}
__device__ __forceinline__ u64 add2(u64 a, u64 b) {
    u64 d; asm("add.rn.f32x2 %0, %1, %2;" : "=l"(d) : "l"(a), "l"(b)); return d;
}
__device__ __forceinline__ u64 pack2(float x, float y) {
    u64 d; asm("mov.b64 %0, {%1, %2};" : "=l"(d) : "f"(x), "f"(y)); return d;
}
__device__ __forceinline__ void unpack2(u64 v, float &x, float &y) {
    asm("mov.b64 {%0, %1}, %2;" : "=f"(x), "=f"(y) : "l"(v));
}

// ---------------- constant-bank weight storage ----------------
struct Consts {
    u64 W[NL][DIM * DIM];   // packed {w,w}
    u64 B[NL][DIM];         // packed {b,b}
    u64 scale[DIM], off[DIM];
};
__device__   Consts g_stage;    // staging (written by prep kernel)
__constant__ Consts c_c;        // read by main kernel via const port

__global__ void prep_kernel(const float* __restrict__ Ws,
                            const float* __restrict__ bs,
                            const float* __restrict__ bounds)
{
    int i = threadIdx.x + blockIdx.x * blockDim.x;
    if (i < NL * DIM * DIM) {
        float w = Ws[i];
        g_stage.W[i / (DIM * DIM)][i % (DIM * DIM)] = pack2(w, w);
    }
    if (i < NL * DIM) {
        float b = bs[i];
        g_stage.B[i / DIM][i % DIM] = pack2(b, b);
    }
    if (i < DIM) {
        float lo = bounds[2 * i];
        float hi = bounds[2 * i + 1];
        float s  = 1.0f / (hi - lo);
        float o  = -lo * s;
        g_stage.scale[i] = pack2(s, s);
        g_stage.off[i]   = pack2(o, o);
    }
}

__global__ void __launch_bounds__(TPB, 2)     // <=128 regs, 16 warps/SM
mlp_kernel(const float* __restrict__ X,
           float* __restrict__ out,
           int B)
{
    long long tid  = (long long)blockIdx.x * blockDim.x + threadIdx.x;
    long long base = tid * ROWS;
    if (base >= B) return;

    // LIN: weights/bias from CONSTANT bank (uniform const port), zero L1 traffic
#define LIN(L, IN, OUT) do {                                                   \
    _Pragma("unroll")                                                          \
    for (int j = 0; j < DIM; j++) {                                            \
        u64 acc[LANES];                                                        \
        u64 bb = c_c.B[(L)][j];                                                \
        _Pragma("unroll")                                                      \
        for (int p = 0; p < LANES; p++) acc[p] = bb;                           \
        _Pragma("unroll")                                                      \
        for (int k = 0; k < DIM; k++) {                                        \
            u64 ww = c_c.W[(L)][j * DIM + k];                                  \
            _Pragma("unroll")                                                  \
            for (int p = 0; p < LANES; p++) acc[p] = fma2(IN[p][k], ww, acc[p]);\
        }                                                                      \
        _Pragma("unroll")                                                      \
        for (int p = 0; p < LANES; p++) OUT[p][j] = acc[p];                    \
    } } while (0)

    // lrelu per half: FMUL-imm (fma pipe, rt=1) + FMNMX (alu pipe, idle)
    // register-pair view; unpack/pack resolves to register naming
#define LRELU(A) do {                                                          \
    _Pragma("unroll")                                                          \
    for (int p = 0; p < LANES; p++) {                                          \
        _Pragma("unroll")                                                      \
        for (int j = 0; j < DIM; j++) {                                        \
            float lo_, hi_;                                                    \
            unpack2(A[p][j], lo_, hi_);                                        \
            lo_ = fmaxf(lo_, 0.01f * lo_);                                     \
            hi_ = fmaxf(hi_, 0.01f * hi_);                                     \
            A[p][j] = pack2(lo_, hi_);                                         \
        }                                                                      \
    } } while (0)

    if (base + ROWS <= B) {
        // ---------- fast path: 4 full rows ----------
        u64 w[LANES][DIM], t[LANES][DIM], res[LANES][DIM];

        const float4* Xv = reinterpret_cast<const float4*>(X + base * DIM);
#pragma unroll
        for (int p = 0; p < LANES; p++) {
            float4 q0 = Xv[3 * p + 0], q1 = Xv[3 * p + 1], q2 = Xv[3 * p + 2];
            w[p][0] = fma2(pack2(q0.x, q1.z), c_c.scale[0], c_c.off[0]);
            w[p][1] = fma2(pack2(q0.y, q1.w), c_c.scale[1], c_c.off[1]);
            w[p][2] = fma2(pack2(q0.z, q2.x), c_c.scale[2], c_c.off[2]);
            w[p][3] = fma2(pack2(q0.w, q2.y), c_c.scale[3], c_c.off[3]);
            w[p][4] = fma2(pack2(q1.x, q2.z), c_c.scale[4], c_c.off[4]);
            w[p][5] = fma2(pack2(q1.y, q2.w), c_c.scale[5], c_c.off[5]);
        }

#pragma unroll
        for (int blk = 0; blk < 4; blk++) {
            const int i0 = blk * 4;
#pragma unroll
            for (int p = 0; p < LANES; p++)
#pragma unroll
                for (int j = 0; j < DIM; j++) res[p][j] = w[p][j];

            LIN(i0 + 0, w, t); LRELU(t);
            LIN(i0 + 1, t, w); LRELU(w);
            LIN(i0 + 2, w, t); LRELU(t);
            LIN(i0 + 3, t, w);
#pragma unroll
            for (int p = 0; p < LANES; p++)
#pragma unroll
                for (int j = 0; j < DIM; j++) w[p][j] = add2(w[p][j], res[p][j]);
        }
        LIN(16, w, t); LRELU(t);
        LIN(17, t, w); LRELU(w);
        LIN(18, w, t);

        float4* Ov = reinterpret_cast<float4*>(out + base * DIM);
#pragma unroll
        for (int p = 0; p < LANES; p++) {
            float a0, b0, a1, b1, a2, b2, a3, b3, a4, b4, a5, b5;
            unpack2(t[p][0], a0, b0); unpack2(t[p][1], a1, b1);
            unpack2(t[p][2], a2, b2); unpack2(t[p][3], a3, b3);
            unpack2(t[p][4], a4, b4); unpack2(t[p][5], a5, b5);
            Ov[3 * p + 0] = make_float4(a0, a1, a2, a3);
            Ov[3 * p + 1] = make_float4(a4, a5, b0, b1);
            Ov[3 * p + 2] = make_float4(b2, b3, b4, b5);
        }
    } else {
        // ---------- tail path: scalar per-row (not taken when B%4==0) ----------
        for (long long r = base; r < B; r++) {
            float x[DIM], y[DIM], rs[DIM];
            for (int k = 0; k < DIM; k++) {
                float s, o, dummy;
                unpack2(c_c.scale[k], s, dummy);
                unpack2(c_c.off[k],   o, dummy);
                x[k] = X[r * DIM + k] * s + o;
            }

            auto lin_s = [&](int L, const float* in, float* o) {
                for (int j = 0; j < DIM; j++) {
                    float a, d0;
                    unpack2(c_c.B[L][j], a, d0);
                    for (int k = 0; k < DIM; k++) {
                        float wv, d1;
                        unpack2(c_c.W[L][j * DIM + k], wv, d1);
                        a = fmaf(in[k], wv, a);
                    }
                    o[j] = a;
                }
            };
            auto lrelu_s = [&](float* v) {
                for (int j = 0; j < DIM; j++) v[j] = fmaxf(v[j], 0.01f * v[j]);
            };

            for (int blk = 0; blk < 4; blk++) {
                int i0 = blk * 4;
                for (int k = 0; k < DIM; k++) rs[k] = x[k];
                lin_s(i0 + 0, x, y); lrelu_s(y);
                lin_s(i0 + 1, y, x); lrelu_s(x);
                lin_s(i0 + 2, x, y); lrelu_s(y);
                lin_s(i0 + 3, y, x);
                for (int k = 0; k < DIM; k++) x[k] += rs[k];
            }
            lin_s(16, x, y); lrelu_s(y);
            lin_s(17, y, x); lrelu_s(x);
            lin_s(18, x, y);
            for (int k = 0; k < DIM; k++) out[r * DIM + k] = y[k];
        }
    }
#undef LIN
#undef LRELU
}

extern "C" void kernel_launch(void* const* d_in, const int* in_sizes, int n_in,
                              void* d_out, int out_size)
{
    const float* X      = (const float*)d_in[0];
    const float* Ws     = (const float*)d_in[1];
    const float* bs     = (const float*)d_in[2];
    const float* bounds = (const float*)d_in[3];
    float* out = (float*)d_out;

    int B = in_sizes[0] / DIM;

    // 1) pack weights into staging struct (device global, no alloc)
    prep_kernel<<<3, 256>>>(Ws, bs, bounds);

    // 2) staging -> constant bank (D2D memcpy node, graph-capturable)
    void* stage_ptr = nullptr;
    cudaGetSymbolAddress(&stage_ptr, g_stage);
    cudaMemcpyToSymbolAsync(c_c, stage_ptr, sizeof(Consts), 0,
                            cudaMemcpyDeviceToDevice, 0);

    // 3) main kernel
    long long tiles = ((long long)B + ROWS - 1) / ROWS;
    int blocks = (int)((tiles + TPB - 1) / TPB);
    mlp_kernel<<<blocks, TPB>>>(X, out, B);
}

// round 10
// speedup vs baseline: 1.2841x; 1.0543x over previous
#include <cuda_runtime.h>

typedef unsigned long long u64;

#define NL    19
#define DIM   6
#define LANES 2                 // packed f32x2 lanes per thread
#define ROWS  (2 * LANES)       // 4 rows per thread
#define TPB   128

// ---------------- packed f32x2 helpers (Blackwell sm_103a) ----------------
__device__ __forceinline__ u64 fma2(u64 a, u64 b, u64 c) {
    u64 d; asm("fma.rn.f32x2 %0, %1, %2, %3;" : "=l"(d) : "l"(a), "l"(b), "l"(c)); return d;
}
__device__ __forceinline__ u64 add2(u64 a, u64 b) {
    u64 d; asm("add.rn.f32x2 %0, %1, %2;" : "=l"(d) : "l"(a), "l"(b)); return d;
}
__device__ __forceinline__ u64 pack2(float x, float y) {
    u64 d; asm("mov.b64 %0, {%1, %2};" : "=l"(d) : "f"(x), "f"(y)); return d;
}
__device__ __forceinline__ void unpack2(u64 v, float &x, float &y) {
    asm("mov.b64 {%0, %1}, %2;" : "=f"(x), "=f"(y) : "l"(v));
}

// ---------------- constant-bank weight storage ----------------
struct Consts {
    u64 W[NL][DIM * DIM];   // packed {w,w}
    u64 B[NL][DIM];         // packed {b,b}
    u64 scale[DIM], off[DIM];
};
__device__   Consts g_stage;    // staging (written by prep kernel)
__constant__ Consts c_c;        // read by main kernel via const port

__global__ void prep_kernel(const float* __restrict__ Ws,
                            const float* __restrict__ bs,
                            const float* __restrict__ bounds)
{
    int i = threadIdx.x + blockIdx.x * blockDim.x;
    if (i < NL * DIM * DIM) {
        float w = Ws[i];
        g_stage.W[i / (DIM * DIM)][i % (DIM * DIM)] = pack2(w, w);
    }
    if (i < NL * DIM) {
        float b = bs[i];
        g_stage.B[i / DIM][i % DIM] = pack2(b, b);
    }
    if (i < DIM) {
        float lo = bounds[2 * i];
        float hi = bounds[2 * i + 1];
        float s  = 1.0f / (hi - lo);
        float o  = -lo * s;
        g_stage.scale[i] = pack2(s, s);
        g_stage.off[i]   = pack2(o, o);
    }
}

__global__ void __launch_bounds__(TPB, 6)     // <=85 regs -> 24 warps/SM
mlp_kernel(const float* __restrict__ X,
           float* __restrict__ out,
           int B)
{
    // residual parking in (now idle) shared: SoA, conflict-free 64-bit lanes
    __shared__ u64 sRes[LANES * DIM][TPB];

    long long tid  = (long long)blockIdx.x * blockDim.x + threadIdx.x;
    long long base = tid * ROWS;
    if (base >= B) return;
    const int lt = threadIdx.x;

    // LIN: weights/bias from CONSTANT bank (uniform const port), zero L1 traffic
#define LIN(L, IN, OUT) do {                                                   \
    _Pragma("unroll")                                                          \
    for (int j = 0; j < DIM; j++) {                                            \
        u64 acc[LANES];                                                        \
        u64 bb = c_c.B[(L)][j];                                                \
        _Pragma("unroll")                                                      \
        for (int p = 0; p < LANES; p++) acc[p] = bb;                           \
        _Pragma("unroll")                                                      \
        for (int k = 0; k < DIM; k++) {                                        \
            u64 ww = c_c.W[(L)][j * DIM + k];                                  \
            _Pragma("unroll")                                                  \
            for (int p = 0; p < LANES; p++) acc[p] = fma2(IN[p][k], ww, acc[p]);\
        }                                                                      \
        _Pragma("unroll")                                                      \
        for (int p = 0; p < LANES; p++) OUT[p][j] = acc[p];                    \
    } } while (0)

    // lrelu per half: FMUL-imm (fma pipe, rt=1) + FMNMX (alu pipe)
#define LRELU(A) do {                                                          \
    _Pragma("unroll")                                                          \
    for (int p = 0; p < LANES; p++) {                                          \
        _Pragma("unroll")                                                      \
        for (int j = 0; j < DIM; j++) {                                        \
            float lo_, hi_;                                                    \
            unpack2(A[p][j], lo_, hi_);                                        \
            lo_ = fmaxf(lo_, 0.01f * lo_);                                     \
            hi_ = fmaxf(hi_, 0.01f * hi_);                                     \
            A[p][j] = pack2(lo_, hi_);                                         \
        }                                                                      \
    } } while (0)

    if (base + ROWS <= B) {
        // ---------- fast path: 4 full rows ----------
        u64 w[LANES][DIM], t[LANES][DIM];

        const float4* Xv = reinterpret_cast<const float4*>(X + base * DIM);
#pragma unroll
        for (int p = 0; p < LANES; p++) {
            float4 q0 = Xv[3 * p + 0], q1 = Xv[3 * p + 1], q2 = Xv[3 * p + 2];
            w[p][0] = fma2(pack2(q0.x, q1.z), c_c.scale[0], c_c.off[0]);
            w[p][1] = fma2(pack2(q0.y, q1.w), c_c.scale[1], c_c.off[1]);
            w[p][2] = fma2(pack2(q0.z, q2.x), c_c.scale[2], c_c.off[2]);
            w[p][3] = fma2(pack2(q0.w, q2.y), c_c.scale[3], c_c.off[3]);
            w[p][4] = fma2(pack2(q1.x, q2.z), c_c.scale[4], c_c.off[4]);
            w[p][5] = fma2(pack2(q1.y, q2.w), c_c.scale[5], c_c.off[5]);
        }

#pragma unroll
        for (int blk = 0; blk < 4; blk++) {
            const int i0 = blk * 4;
            // park residual in shared (frees 24 regs of live state)
#pragma unroll
            for (int p = 0; p < LANES; p++)
#pragma unroll
                for (int j = 0; j < DIM; j++) sRes[p * DIM + j][lt] = w[p][j];

            LIN(i0 + 0, w, t); LRELU(t);
            LIN(i0 + 1, t, w); LRELU(w);
            LIN(i0 + 2, w, t); LRELU(t);
            LIN(i0 + 3, t, w);
#pragma unroll
            for (int p = 0; p < LANES; p++)
#pragma unroll
                for (int j = 0; j < DIM; j++)
                    w[p][j] = add2(w[p][j], sRes[p * DIM + j][lt]);
        }
        LIN(16, w, t); LRELU(t);
        LIN(17, t, w); LRELU(w);
        LIN(18, w, t);

        float4* Ov = reinterpret_cast<float4*>(out + base * DIM);
#pragma unroll
        for (int p = 0; p < LANES; p++) {
            float a0, b0, a1, b1, a2, b2, a3, b3, a4, b4, a5, b5;
            unpack2(t[p][0], a0, b0); unpack2(t[p][1], a1, b1);
            unpack2(t[p][2], a2, b2); unpack2(t[p][3], a3, b3);
            unpack2(t[p][4], a4, b4); unpack2(t[p][5], a5, b5);
            Ov[3 * p + 0] = make_float4(a0, a1, a2, a3);
            Ov[3 * p + 1] = make_float4(a4, a5, b0, b1);
            Ov[3 * p + 2] = make_float4(b2, b3, b4, b5);
        }
    } else {
        // ---------- tail path: scalar per-row (not taken when B%4==0) ----------
        for (long long r = base; r < B; r++) {
            float x[DIM], y[DIM], rs[DIM];
            for (int k = 0; k < DIM; k++) {
                float s, o, dummy;
                unpack2(c_c.scale[k], s, dummy);
                unpack2(c_c.off[k],   o, dummy);
                x[k] = X[r * DIM + k] * s + o;
            }

            auto lin_s = [&](int L, const float* in, float* o) {
                for (int j = 0; j < DIM; j++) {
                    float a, d0;
                    unpack2(c_c.B[L][j], a, d0);
                    for (int k = 0; k < DIM; k++) {
                        float wv, d1;
                        unpack2(c_c.W[L][j * DIM + k], wv, d1);
                        a = fmaf(in[k], wv, a);
                    }
                    o[j] = a;
                }
            };
            auto lrelu_s = [&](float* v) {
                for (int j = 0; j < DIM; j++) v[j] = fmaxf(v[j], 0.01f * v[j]);
            };

            for (int blk = 0; blk < 4; blk++) {
                int i0 = blk * 4;
                for (int k = 0; k < DIM; k++) rs[k] = x[k];
                lin_s(i0 + 0, x, y); lrelu_s(y);
                lin_s(i0 + 1, y, x); lrelu_s(x);
                lin_s(i0 + 2, x, y); lrelu_s(y);
                lin_s(i0 + 3, y, x);
                for (int k = 0; k < DIM; k++) x[k] += rs[k];
            }
            lin_s(16, x, y); lrelu_s(y);
            lin_s(17, y, x); lrelu_s(x);
            lin_s(18, x, y);
            for (int k = 0; k < DIM; k++) out[r * DIM + k] = y[k];
        }
    }
#undef LIN
#undef LRELU
}

extern "C" void kernel_launch(void* const* d_in, const int* in_sizes, int n_in,
                              void* d_out, int out_size)
{
    const float* X      = (const float*)d_in[0];
    const float* Ws     = (const float*)d_in[1];
    const float* bs     = (const float*)d_in[2];
    const float* bounds = (const float*)d_in[3];
    float* out = (float*)d_out;

    int B = in_sizes[0] / DIM;

    // 1) pack weights into staging struct (device global, no alloc)
    prep_kernel<<<3, 256>>>(Ws, bs, bounds);

    // 2) staging -> constant bank (D2D memcpy node, graph-capturable)
    void* stage_ptr = nullptr;
    cudaGetSymbolAddress(&stage_ptr, g_stage);
    cudaMemcpyToSymbolAsync(c_c, stage_ptr, sizeof(Consts), 0,
                            cudaMemcpyDeviceToDevice, 0);

    // 3) main kernel
    long long tiles = ((long long)B + ROWS - 1) / ROWS;
    int blocks = (int)((tiles + TPB - 1) / TPB);
    mlp_kernel<<<blocks, TPB>>>(X, out, B);
}